// round 2
// baseline (speedup 1.0000x reference)
#include <cuda_runtime.h>
#include <cstdint>

// Problem constants (shapes are fixed by the dataset).
constexpr int Hdim   = 128;
constexpr int NLEAF  = 8192;
constexpr int NBATCH = 8;
constexpr int NL     = NBATCH * NLEAF;     // 65536 leaf edges
constexpr int NPT    = 24575;              // nodes per tree
constexpr int NN     = NBATCH * NPT;       // 196600 total nodes
constexpr int DEPTH  = 14;

constexpr int TILE_R     = 64;
constexpr int ASTR_BIG   = 260;            // smem stride for 256-wide inputs (pad for banks)
constexpr int ASTR_SMALL = 132;            // smem stride for 128/129-wide
constexpr int SMEM_FLOATS = TILE_R * ASTR_BIG + 64 * Hdim;  // A/H buffer + W chunk
constexpr int SMEM_BYTES  = SMEM_FLOATS * 4;                // 99328 B

// Accumulate acc[4][8] += A_tile @ W  for one layer.
// sA: [64][ASTR] activations, sW: 64x128 weight-chunk staging.
template<int K, int ASTR>
__device__ __forceinline__ void layer_acc(const float* __restrict__ sA,
                                          float* __restrict__ sW,
                                          const float* __restrict__ w,
                                          int tid, int r0, int c0,
                                          float (&acc)[4][8])
{
#pragma unroll
    for (int k0 = 0; k0 < K; k0 += 64) {
        const int kk = (K - k0 < 64) ? (K - k0) : 64;
        // stage weight chunk kk x 128 into smem
        for (int idx = tid; idx < kk * 32; idx += 256) {
            int kr = idx >> 5, c4 = idx & 31;
            reinterpret_cast<float4*>(sW)[idx] =
                reinterpret_cast<const float4*>(w + (size_t)(k0 + kr) * Hdim)[c4];
        }
        __syncthreads();
#pragma unroll 8
        for (int k = 0; k < kk; ++k) {
            float a0 = sA[(r0 + 0) * ASTR + k0 + k];
            float a1 = sA[(r0 + 1) * ASTR + k0 + k];
            float a2 = sA[(r0 + 2) * ASTR + k0 + k];
            float a3 = sA[(r0 + 3) * ASTR + k0 + k];
            float4 wv0 = *reinterpret_cast<const float4*>(sW + k * Hdim + c0);
            float4 wv1 = *reinterpret_cast<const float4*>(sW + k * Hdim + c0 + 4);
            const float wv[8] = {wv0.x, wv0.y, wv0.z, wv0.w, wv1.x, wv1.y, wv1.z, wv1.w};
#pragma unroll
            for (int j = 0; j < 8; ++j) {
                acc[0][j] = fmaf(a0, wv[j], acc[0][j]);
                acc[1][j] = fmaf(a1, wv[j], acc[1][j]);
                acc[2][j] = fmaf(a2, wv[j], acc[2][j]);
                acc[3][j] = fmaf(a3, wv[j], acc[3][j]);
            }
        }
        __syncthreads();
    }
}

__device__ __forceinline__ void zero_acc(float (&acc)[4][8]) {
#pragma unroll
    for (int i = 0; i < 4; ++i)
#pragma unroll
        for (int j = 0; j < 8; ++j) acc[i][j] = 0.f;
}

// MODE 0: nem  — in = [x[esrc[e]], ef[e]]          (K=256), out -> x[edst[e]]       (set)
// MODE 1: mg   — in = [x[esrc[s+r]], x[esrc[s+half+r]]] (K=256), out -> x[edst[s+half+r]] (set)
// MODE 2: mr   — in = [x[edst[e]], state[e]]        (K=129), out -> x[esrc[e]] += out
template<int MODE>
__global__ void __launch_bounds__(256)
mlp_kernel(float* __restrict__ x,
           const float* __restrict__ ef,
           const int* __restrict__ esrc,
           const int* __restrict__ edst,
           const float* __restrict__ est,
           const float* __restrict__ w0, const float* __restrict__ b0,
           const float* __restrict__ w1, const float* __restrict__ b1,
           const float* __restrict__ w2, const float* __restrict__ b2,
           int s, int half, int nrows)
{
    extern __shared__ float sm[];
    float* sA = sm;
    float* sW = sm + TILE_R * ASTR_BIG;

    const int tid = threadIdx.x;
    const int cx = tid & 15, ry = tid >> 4;
    const int c0 = cx * 8, r0 = ry * 4;
    const int row_base = blockIdx.x * TILE_R;

    // ---- gather inputs into sA ----
    if (MODE == 0 || MODE == 1) {
        for (int idx = tid; idx < TILE_R * 64; idx += 256) {
            int r = idx >> 6, c4 = idx & 63;
            int row = row_base + r;
            if (row < nrows) {
                float4 v;
                if (c4 < 32) {
                    int e = s + row;
                    int node = esrc[e];
                    v = reinterpret_cast<const float4*>(x + (size_t)node * Hdim)[c4];
                } else if (MODE == 0) {
                    int e = s + row;
                    v = reinterpret_cast<const float4*>(ef + (size_t)e * Hdim)[c4 - 32];
                } else {
                    int e = s + half + row;
                    int node = esrc[e];
                    v = reinterpret_cast<const float4*>(x + (size_t)node * Hdim)[c4 - 32];
                }
                reinterpret_cast<float4*>(sA + r * ASTR_BIG)[c4] = v;
            }
        }
    } else {
        for (int idx = tid; idx < TILE_R * 32; idx += 256) {
            int r = idx >> 5, c4 = idx & 31;
            int row = row_base + r;
            if (row < nrows) {
                int e = s + row;
                int node = edst[e];
                float4 v = reinterpret_cast<const float4*>(x + (size_t)node * Hdim)[c4];
                reinterpret_cast<float4*>(sA + r * ASTR_SMALL)[c4] = v;
            }
        }
        for (int r = tid; r < TILE_R; r += 256) {
            int row = row_base + r;
            if (row < nrows) sA[r * ASTR_SMALL + 128] = est[s + row];
        }
    }
    __syncthreads();

    float acc[4][8];

    // ---- layer 0 ----
    zero_acc(acc);
    if (MODE == 2) layer_acc<129, ASTR_SMALL>(sA, sW, w0, tid, r0, c0, acc);
    else           layer_acc<256, ASTR_BIG  >(sA, sW, w0, tid, r0, c0, acc);
    {
        float4 bv0 = *reinterpret_cast<const float4*>(b0 + c0);
        float4 bv1 = *reinterpret_cast<const float4*>(b0 + c0 + 4);
        const float bv[8] = {bv0.x, bv0.y, bv0.z, bv0.w, bv1.x, bv1.y, bv1.z, bv1.w};
#pragma unroll
        for (int i = 0; i < 4; ++i) {
#pragma unroll
            for (int j = 0; j < 8; ++j) {
                float v = acc[i][j] + bv[j];
                acc[i][j] = v > 0.f ? v : 0.f;
            }
            // layer_acc ended with __syncthreads(): safe to overwrite sA now
            *reinterpret_cast<float4*>(sA + (r0 + i) * ASTR_SMALL + c0) =
                make_float4(acc[i][0], acc[i][1], acc[i][2], acc[i][3]);
            *reinterpret_cast<float4*>(sA + (r0 + i) * ASTR_SMALL + c0 + 4) =
                make_float4(acc[i][4], acc[i][5], acc[i][6], acc[i][7]);
        }
    }
    __syncthreads();

    // ---- layer 1 ----
    zero_acc(acc);
    layer_acc<128, ASTR_SMALL>(sA, sW, w1, tid, r0, c0, acc);
    {
        float4 bv0 = *reinterpret_cast<const float4*>(b1 + c0);
        float4 bv1 = *reinterpret_cast<const float4*>(b1 + c0 + 4);
        const float bv[8] = {bv0.x, bv0.y, bv0.z, bv0.w, bv1.x, bv1.y, bv1.z, bv1.w};
#pragma unroll
        for (int i = 0; i < 4; ++i) {
#pragma unroll
            for (int j = 0; j < 8; ++j) {
                float v = acc[i][j] + bv[j];
                acc[i][j] = v > 0.f ? v : 0.f;
            }
            *reinterpret_cast<float4*>(sA + (r0 + i) * ASTR_SMALL + c0) =
                make_float4(acc[i][0], acc[i][1], acc[i][2], acc[i][3]);
            *reinterpret_cast<float4*>(sA + (r0 + i) * ASTR_SMALL + c0 + 4) =
                make_float4(acc[i][4], acc[i][5], acc[i][6], acc[i][7]);
        }
    }
    __syncthreads();

    // ---- layer 2 + scatter ----
    zero_acc(acc);
    layer_acc<128, ASTR_SMALL>(sA, sW, w2, tid, r0, c0, acc);
    {
        float4 bv0 = *reinterpret_cast<const float4*>(b2 + c0);
        float4 bv1 = *reinterpret_cast<const float4*>(b2 + c0 + 4);
        const float bv[8] = {bv0.x, bv0.y, bv0.z, bv0.w, bv1.x, bv1.y, bv1.z, bv1.w};
#pragma unroll
        for (int i = 0; i < 4; ++i) {
            int row = row_base + r0 + i;
            if (row >= nrows) continue;
#pragma unroll
            for (int j = 0; j < 8; ++j) acc[i][j] += bv[j];

            int node;
            if (MODE == 0)      node = edst[s + row];
            else if (MODE == 1) node = edst[s + half + row];
            else                node = esrc[s + row];

            float* p = x + (size_t)node * Hdim + c0;
            if (MODE == 2) {
                float4 o0 = *reinterpret_cast<const float4*>(p);
                float4 o1 = *reinterpret_cast<const float4*>(p + 4);
                acc[i][0] += o0.x; acc[i][1] += o0.y; acc[i][2] += o0.z; acc[i][3] += o0.w;
                acc[i][4] += o1.x; acc[i][5] += o1.y; acc[i][6] += o1.z; acc[i][7] += o1.w;
            }
            *reinterpret_cast<float4*>(p) =
                make_float4(acc[i][0], acc[i][1], acc[i][2], acc[i][3]);
            *reinterpret_cast<float4*>(p + 4) =
                make_float4(acc[i][4], acc[i][5], acc[i][6], acc[i][7]);
        }
    }
}

extern "C" void kernel_launch(void* const* d_in, const int* in_sizes, int n_in,
                              void* d_out, int out_size)
{
    (void)n_in; (void)out_size;

    const float* x_in = (const float*)d_in[0];
    const int*   esrc = (const int*)  d_in[1];
    const int*   edst = (const int*)  d_in[2];
    const float* est  = (const float*)d_in[3];
    const float* ef   = (const float*)d_in[4];

    // Input 5 is the scalar gcmn_depth (size 1); weights start after it.
    // Be defensive in case the harness drops scalar inputs.
    int wb = (in_sizes[5] == 1) ? 6 : 5;

    const float* nem_w0 = (const float*)d_in[wb + 0];
    const float* nem_b0 = (const float*)d_in[wb + 1];
    const float* nem_w1 = (const float*)d_in[wb + 2];
    const float* nem_b1 = (const float*)d_in[wb + 3];
    const float* nem_w2 = (const float*)d_in[wb + 4];
    const float* nem_b2 = (const float*)d_in[wb + 5];
    const float* mg_w0  = (const float*)d_in[wb + 6];
    const float* mg_b0  = (const float*)d_in[wb + 7];
    const float* mg_w1  = (const float*)d_in[wb + 8];
    const float* mg_b1  = (const float*)d_in[wb + 9];
    const float* mg_w2  = (const float*)d_in[wb + 10];
    const float* mg_b2  = (const float*)d_in[wb + 11];
    const float* mr_w0  = (const float*)d_in[wb + 12];
    const float* mr_b0  = (const float*)d_in[wb + 13];
    const float* mr_w1  = (const float*)d_in[wb + 14];
    const float* mr_b1  = (const float*)d_in[wb + 15];
    const float* mr_w2  = (const float*)d_in[wb + 16];
    const float* mr_b2  = (const float*)d_in[wb + 17];

    float* x = (float*)d_out;

    cudaFuncSetAttribute(mlp_kernel<0>, cudaFuncAttributeMaxDynamicSharedMemorySize, SMEM_BYTES);
    cudaFuncSetAttribute(mlp_kernel<1>, cudaFuncAttributeMaxDynamicSharedMemorySize, SMEM_BYTES);
    cudaFuncSetAttribute(mlp_kernel<2>, cudaFuncAttributeMaxDynamicSharedMemorySize, SMEM_BYTES);

    // working copy of node features (leaves must keep original values)
    cudaMemcpyAsync(x, x_in, (size_t)NN * Hdim * sizeof(float),
                    cudaMemcpyDeviceToDevice);

    // edge-block layout: block 0 = leaf edges (NL), block d (1..13) = 65536 >> (d-1)
    int cnt[14], st[14];
    cnt[0] = NL; st[0] = 0;
    for (int d = 1; d < DEPTH; ++d) {
        cnt[d] = 8 * (NLEAF >> (d - 1));
        st[d] = st[d - 1] + cnt[d - 1];
    }

    // ---- nem: leaf -> level-1 ----
    mlp_kernel<0><<<(NL + TILE_R - 1) / TILE_R, 256, SMEM_BYTES>>>(
        x, ef, esrc, edst, nullptr,
        nem_w0, nem_b0, nem_w1, nem_b1, nem_w2, nem_b2, 0, 0, NL);

    // ---- mg: upward merge, levels 1..13 (sequential) ----
    for (int d = 1; d < DEPTH; ++d) {
        int half = cnt[d] / 2;
        mlp_kernel<1><<<(half + TILE_R - 1) / TILE_R, 256, SMEM_BYTES>>>(
            x, nullptr, esrc, edst, nullptr,
            mg_w0, mg_b0, mg_w1, mg_b1, mg_w2, mg_b2, st[d], half, half);
    }

    // ---- mr: downward, depth 14..1 (sequential) ----
    for (int depth = DEPTH; depth >= 1; --depth) {
        int sE, m;
        if (depth == 1) { sE = 0; m = NL; }
        else            { sE = st[depth - 1]; m = cnt[depth - 1]; }
        mlp_kernel<2><<<(m + TILE_R - 1) / TILE_R, 256, SMEM_BYTES>>>(
            x, nullptr, esrc, edst, est,
            mr_w0, mr_b0, mr_w1, mr_b1, mr_w2, mr_b2, sE, 0, m);
    }
}

// round 3
// speedup vs baseline: 1.0916x; 1.0916x over previous
#include <cuda_runtime.h>
#include <cstdint>

// Problem constants (shapes fixed by dataset).
constexpr int Hdim   = 128;
constexpr int NLEAF  = 8192;
constexpr int NBATCH = 8;
constexpr int NL     = NBATCH * NLEAF;     // 65536 leaf edges
constexpr int NPT    = 24575;              // nodes per tree
constexpr int NN     = NBATCH * NPT;       // 196600 total nodes
constexpr int DEPTH  = 14;

constexpr int ASTR_BIG   = 260;            // smem stride for 256-wide inputs
constexpr int ASTR_SMALL = 132;            // smem stride for 128/129-wide

constexpr int SMEM_BYTES_64 = (64 * ASTR_BIG + 64 * Hdim) * 4;  // 99328 B
constexpr int SMEM_BYTES_16 = (16 * ASTR_BIG + 64 * Hdim) * 4;  // 49408 B

// ---- one MLP layer: acc[RPT][8] += A_tile @ W, K multiple of 64 ----
template<int K, int ASTR, int RPT>
__device__ __forceinline__ void layer_acc(const float* __restrict__ sA,
                                          float* __restrict__ sW,
                                          const float* __restrict__ w,
                                          int tid, int r0, int c0,
                                          float (&acc)[RPT][8])
{
#pragma unroll
    for (int k0 = 0; k0 < K; k0 += 64) {
        // stage 64x128 weight chunk
        for (int idx = tid; idx < 64 * 32; idx += 256) {
            int kr = idx >> 5, c4 = idx & 31;
            reinterpret_cast<float4*>(sW)[idx] =
                reinterpret_cast<const float4*>(w + (size_t)(k0 + kr) * Hdim)[c4];
        }
        __syncthreads();
#pragma unroll 4
        for (int kq = 0; kq < 16; ++kq) {
            float4 av[RPT];
#pragma unroll
            for (int i = 0; i < RPT; ++i)
                av[i] = *reinterpret_cast<const float4*>(sA + (r0 + i) * ASTR + k0 + kq * 4);
#pragma unroll
            for (int t = 0; t < 4; ++t) {
                const float* wr = sW + (kq * 4 + t) * Hdim + c0;
                float4 w0v = *reinterpret_cast<const float4*>(wr);
                float4 w1v = *reinterpret_cast<const float4*>(wr + 4);
                const float wv[8] = {w0v.x, w0v.y, w0v.z, w0v.w,
                                     w1v.x, w1v.y, w1v.z, w1v.w};
#pragma unroll
                for (int i = 0; i < RPT; ++i) {
                    float a = reinterpret_cast<const float*>(&av[i])[t];
#pragma unroll
                    for (int j = 0; j < 8; ++j)
                        acc[i][j] = fmaf(a, wv[j], acc[i][j]);
                }
            }
        }
        __syncthreads();
    }
}

template<int RPT>
__device__ __forceinline__ void zero_acc(float (&acc)[RPT][8]) {
#pragma unroll
    for (int i = 0; i < RPT; ++i)
#pragma unroll
        for (int j = 0; j < 8; ++j) acc[i][j] = 0.f;
}

template<int RPT>
__device__ __forceinline__ void bias_relu_store(float (&acc)[RPT][8],
                                                const float* __restrict__ b,
                                                float* __restrict__ sA,
                                                int r0, int c0)
{
    float4 bv0 = *reinterpret_cast<const float4*>(b + c0);
    float4 bv1 = *reinterpret_cast<const float4*>(b + c0 + 4);
    const float bv[8] = {bv0.x, bv0.y, bv0.z, bv0.w, bv1.x, bv1.y, bv1.z, bv1.w};
#pragma unroll
    for (int i = 0; i < RPT; ++i) {
#pragma unroll
        for (int j = 0; j < 8; ++j) {
            float v = acc[i][j] + bv[j];
            acc[i][j] = v > 0.f ? v : 0.f;
        }
        *reinterpret_cast<float4*>(sA + (r0 + i) * ASTR_SMALL + c0) =
            make_float4(acc[i][0], acc[i][1], acc[i][2], acc[i][3]);
        *reinterpret_cast<float4*>(sA + (r0 + i) * ASTR_SMALL + c0 + 4) =
            make_float4(acc[i][4], acc[i][5], acc[i][6], acc[i][7]);
    }
}

// MODE 0: nem — in = [x[esrc[e]], ef[e]]              (K=256), out -> x[edst[e]]        (set)
// MODE 1: mg  — in = [x[esrc[s+r]], x[esrc[s+half+r]]](K=256), out -> x[edst[s+half+r]] (set)
// MODE 2: mr  — in = [x[edst[e]], state[e]]           (K=129), out -> x[esrc[e]] += out
template<int MODE, int TR>
__global__ void __launch_bounds__(256)
mlp_kernel(float* __restrict__ x,
           const float* __restrict__ ef,
           const int* __restrict__ esrc,
           const int* __restrict__ edst,
           const float* __restrict__ est,
           const float* __restrict__ w0, const float* __restrict__ b0,
           const float* __restrict__ w1, const float* __restrict__ b1,
           const float* __restrict__ w2, const float* __restrict__ b2,
           int s, int half, int nrows)
{
    constexpr int RPT = TR / 16;
    extern __shared__ float sm[];
    float* sA = sm;
    float* sW = sm + TR * ASTR_BIG;

    const int tid = threadIdx.x;
    const int cx = tid & 15, ry = tid >> 4;
    const int c0 = cx * 8, r0 = ry * RPT;
    const int row_base = blockIdx.x * TR;

    // ---- gather inputs into sA ----
    if (MODE == 0 || MODE == 1) {
        for (int idx = tid; idx < TR * 64; idx += 256) {
            int r = idx >> 6, c4 = idx & 63;
            int row = row_base + r;
            if (row < nrows) {
                float4 v;
                if (c4 < 32) {
                    int node = esrc[s + row];
                    v = reinterpret_cast<const float4*>(x + (size_t)node * Hdim)[c4];
                } else if (MODE == 0) {
                    v = reinterpret_cast<const float4*>(ef + (size_t)(s + row) * Hdim)[c4 - 32];
                } else {
                    int node = esrc[s + half + row];
                    v = reinterpret_cast<const float4*>(x + (size_t)node * Hdim)[c4 - 32];
                }
                reinterpret_cast<float4*>(sA + r * ASTR_BIG)[c4] = v;
            }
        }
    } else {
        for (int idx = tid; idx < TR * 32; idx += 256) {
            int r = idx >> 5, c4 = idx & 31;
            int row = row_base + r;
            if (row < nrows) {
                int node = edst[s + row];
                float4 v = reinterpret_cast<const float4*>(x + (size_t)node * Hdim)[c4];
                reinterpret_cast<float4*>(sA + r * ASTR_SMALL)[c4] = v;
            }
        }
        for (int r = tid; r < TR; r += 256) {
            int row = row_base + r;
            sA[r * ASTR_SMALL + 128] = (row < nrows) ? est[s + row] : 0.f;
        }
    }
    __syncthreads();

    float acc[RPT][8];

    // ---- layer 0 ----
    zero_acc<RPT>(acc);
    if (MODE == 2) {
        layer_acc<128, ASTR_SMALL, RPT>(sA, sW, w0, tid, r0, c0, acc);
        // state column (row 128 of w0): broadcast from global (L2/const-cached)
        float4 wsa = *reinterpret_cast<const float4*>(w0 + (size_t)128 * Hdim + c0);
        float4 wsb = *reinterpret_cast<const float4*>(w0 + (size_t)128 * Hdim + c0 + 4);
        const float ws[8] = {wsa.x, wsa.y, wsa.z, wsa.w, wsb.x, wsb.y, wsb.z, wsb.w};
#pragma unroll
        for (int i = 0; i < RPT; ++i) {
            float stv = sA[(r0 + i) * ASTR_SMALL + 128];
#pragma unroll
            for (int j = 0; j < 8; ++j)
                acc[i][j] = fmaf(stv, ws[j], acc[i][j]);
        }
        __syncthreads();   // everyone done reading sA layer-0 inputs
    } else {
        layer_acc<256, ASTR_BIG, RPT>(sA, sW, w0, tid, r0, c0, acc);
    }
    bias_relu_store<RPT>(acc, b0, sA, r0, c0);
    __syncthreads();

    // ---- layer 1 ----
    zero_acc<RPT>(acc);
    layer_acc<128, ASTR_SMALL, RPT>(sA, sW, w1, tid, r0, c0, acc);
    bias_relu_store<RPT>(acc, b1, sA, r0, c0);
    __syncthreads();

    // ---- layer 2 + scatter ----
    zero_acc<RPT>(acc);
    layer_acc<128, ASTR_SMALL, RPT>(sA, sW, w2, tid, r0, c0, acc);
    {
        float4 bv0 = *reinterpret_cast<const float4*>(b2 + c0);
        float4 bv1 = *reinterpret_cast<const float4*>(b2 + c0 + 4);
        const float bv[8] = {bv0.x, bv0.y, bv0.z, bv0.w, bv1.x, bv1.y, bv1.z, bv1.w};
#pragma unroll
        for (int i = 0; i < RPT; ++i) {
            int row = row_base + r0 + i;
            if (row >= nrows) continue;
#pragma unroll
            for (int j = 0; j < 8; ++j) acc[i][j] += bv[j];

            int node;
            if (MODE == 0)      node = edst[s + row];
            else if (MODE == 1) node = edst[s + half + row];
            else                node = esrc[s + row];

            float* p = x + (size_t)node * Hdim + c0;
            if (MODE == 2) {
                float4 o0 = *reinterpret_cast<const float4*>(p);
                float4 o1 = *reinterpret_cast<const float4*>(p + 4);
                acc[i][0] += o0.x; acc[i][1] += o0.y; acc[i][2] += o0.z; acc[i][3] += o0.w;
                acc[i][4] += o1.x; acc[i][5] += o1.y; acc[i][6] += o1.z; acc[i][7] += o1.w;
            }
            *reinterpret_cast<float4*>(p) =
                make_float4(acc[i][0], acc[i][1], acc[i][2], acc[i][3]);
            *reinterpret_cast<float4*>(p + 4) =
                make_float4(acc[i][4], acc[i][5], acc[i][6], acc[i][7]);
        }
    }
}

// copy only leaf rows of x (everything else is provably overwritten)
__global__ void leaf_copy_kernel(float* __restrict__ x, const float* __restrict__ x_in)
{
    int idx = blockIdx.x * blockDim.x + threadIdx.x;   // over NL*32 float4s
    if (idx >= NL * 32) return;
    int r = idx >> 5, c4 = idx & 31;
    int b = r >> 13, leaf = r & (NLEAF - 1);           // NLEAF = 8192 = 2^13
    size_t node = (size_t)b * NPT + leaf;
    reinterpret_cast<float4*>(x + node * Hdim)[c4] =
        reinterpret_cast<const float4*>(x_in + node * Hdim)[c4];
}

extern "C" void kernel_launch(void* const* d_in, const int* in_sizes, int n_in,
                              void* d_out, int out_size)
{
    (void)n_in; (void)out_size;

    const float* x_in = (const float*)d_in[0];
    const int*   esrc = (const int*)  d_in[1];
    const int*   edst = (const int*)  d_in[2];
    const float* est  = (const float*)d_in[3];
    const float* ef   = (const float*)d_in[4];

    // Input 5 is scalar gcmn_depth (size 1); weights start after it.
    int wb = (in_sizes[5] == 1) ? 6 : 5;

    const float* nem_w0 = (const float*)d_in[wb + 0];
    const float* nem_b0 = (const float*)d_in[wb + 1];
    const float* nem_w1 = (const float*)d_in[wb + 2];
    const float* nem_b1 = (const float*)d_in[wb + 3];
    const float* nem_w2 = (const float*)d_in[wb + 4];
    const float* nem_b2 = (const float*)d_in[wb + 5];
    const float* mg_w0  = (const float*)d_in[wb + 6];
    const float* mg_b0  = (const float*)d_in[wb + 7];
    const float* mg_w1  = (const float*)d_in[wb + 8];
    const float* mg_b1  = (const float*)d_in[wb + 9];
    const float* mg_w2  = (const float*)d_in[wb + 10];
    const float* mg_b2  = (const float*)d_in[wb + 11];
    const float* mr_w0  = (const float*)d_in[wb + 12];
    const float* mr_b0  = (const float*)d_in[wb + 13];
    const float* mr_w1  = (const float*)d_in[wb + 14];
    const float* mr_b1  = (const float*)d_in[wb + 15];
    const float* mr_w2  = (const float*)d_in[wb + 16];
    const float* mr_b2  = (const float*)d_in[wb + 17];

    float* x = (float*)d_out;

    cudaFuncSetAttribute(mlp_kernel<0,64>, cudaFuncAttributeMaxDynamicSharedMemorySize, SMEM_BYTES_64);
    cudaFuncSetAttribute(mlp_kernel<1,64>, cudaFuncAttributeMaxDynamicSharedMemorySize, SMEM_BYTES_64);
    cudaFuncSetAttribute(mlp_kernel<2,64>, cudaFuncAttributeMaxDynamicSharedMemorySize, SMEM_BYTES_64);
    cudaFuncSetAttribute(mlp_kernel<1,16>, cudaFuncAttributeMaxDynamicSharedMemorySize, SMEM_BYTES_16);
    cudaFuncSetAttribute(mlp_kernel<2,16>, cudaFuncAttributeMaxDynamicSharedMemorySize, SMEM_BYTES_16);

    // init: only leaf rows need the original x
    leaf_copy_kernel<<<(NL * 32 + 255) / 256, 256>>>(x, x_in);

    // edge-block layout: block 0 = leaf edges (NL), block d (1..13) = 65536 >> (d-1)
    int cnt[14], st[14];
    cnt[0] = NL; st[0] = 0;
    for (int d = 1; d < DEPTH; ++d) {
        cnt[d] = 8 * (NLEAF >> (d - 1));
        st[d] = st[d - 1] + cnt[d - 1];
    }

    constexpr int SMALL_THRESH = 2048;

    // ---- nem: leaf -> level-1 ----
    mlp_kernel<0,64><<<(NL + 63) / 64, 256, SMEM_BYTES_64>>>(
        x, ef, esrc, edst, nullptr,
        nem_w0, nem_b0, nem_w1, nem_b1, nem_w2, nem_b2, 0, 0, NL);

    // ---- mg: upward merge, levels 1..13 (sequential) ----
    for (int d = 1; d < DEPTH; ++d) {
        int half = cnt[d] / 2;
        if (half <= SMALL_THRESH)
            mlp_kernel<1,16><<<(half + 15) / 16, 256, SMEM_BYTES_16>>>(
                x, nullptr, esrc, edst, nullptr,
                mg_w0, mg_b0, mg_w1, mg_b1, mg_w2, mg_b2, st[d], half, half);
        else
            mlp_kernel<1,64><<<(half + 63) / 64, 256, SMEM_BYTES_64>>>(
                x, nullptr, esrc, edst, nullptr,
                mg_w0, mg_b0, mg_w1, mg_b1, mg_w2, mg_b2, st[d], half, half);
    }

    // ---- mr: downward, depth 14..1 (sequential) ----
    for (int depth = DEPTH; depth >= 1; --depth) {
        int sE, m;
        if (depth == 1) { sE = 0; m = NL; }
        else            { sE = st[depth - 1]; m = cnt[depth - 1]; }
        if (m <= SMALL_THRESH)
            mlp_kernel<2,16><<<(m + 15) / 16, 256, SMEM_BYTES_16>>>(
                x, nullptr, esrc, edst, est,
                mr_w0, mr_b0, mr_w1, mr_b1, mr_w2, mr_b2, sE, 0, m);
        else
            mlp_kernel<2,64><<<(m + 63) / 64, 256, SMEM_BYTES_64>>>(
                x, nullptr, esrc, edst, est,
                mr_w0, mr_b0, mr_w1, mr_b1, mr_w2, mr_b2, sE, 0, m);
    }
}

// round 4
// speedup vs baseline: 1.3737x; 1.2584x over previous
#include <cuda_runtime.h>
#include <cstdint>

// Problem constants (shapes fixed by dataset).
constexpr int Hdim   = 128;
constexpr int NLEAF  = 8192;
constexpr int NBATCH = 8;
constexpr int NL     = NBATCH * NLEAF;     // 65536 leaf edges
constexpr int NPT    = 24575;              // nodes per tree
constexpr int NN     = NBATCH * NPT;       // 196600 total nodes
constexpr int DEPTH  = 14;

constexpr int ASTR_BIG   = 260;            // smem stride for 256-wide inputs
constexpr int ASTR_SMALL = 132;            // smem stride for 128/129-wide

// big kernel smem
constexpr int SMEM_BIG_01 = (64 * ASTR_BIG   + 64 * Hdim) * 4;  // 99328 B
constexpr int SMEM_BIG_2  = (64 * ASTR_SMALL + 64 * Hdim) * 4;  // 66560 B
// small kernel smem
constexpr int SMEM_SMALL  = (16 * ASTR_BIG   + 64 * Hdim) * 4;  // 49408 B

// ---------------- packed fp32x2 helpers (Blackwell FFMA2) ----------------
typedef unsigned long long ull;

#define FMA_F32X2(d, a, b, c) \
    asm("fma.rn.f32x2 %0, %1, %2, %3;" : "=l"(d) : "l"(a), "l"(b), "l"(c))

#define PACK_DUP_F32X2(out, x) \
    asm("mov.b64 %0, {%1, %1};" : "=l"(out) : "r"(__float_as_uint(x)))

#define UNPACK_F32X2(lo, hi, v) \
    asm("mov.b64 {%0, %1}, %2;" : "=f"(lo), "=f"(hi) : "l"(v))

// =============== BIG kernel: 64-row tiles, 128 threads, 8x8/thread =========

// acc[8][4] f32x2 pairs (8 rows x 8 cols). K multiple of 64.
template<int K, int ASTR>
__device__ __forceinline__ void layer_acc2(const float* __restrict__ sA,
                                           float* __restrict__ sW,
                                           const float* __restrict__ w,
                                           int tid, int r0, int c0,
                                           ull (&acc)[8][4])
{
#pragma unroll 1
    for (int k0 = 0; k0 < K; k0 += 64) {
        // stage 64x128 weight chunk
        for (int idx = tid; idx < 64 * 32; idx += 128) {
            reinterpret_cast<float4*>(sW)[idx] =
                reinterpret_cast<const float4*>(w + (size_t)k0 * Hdim)[idx];
        }
        __syncthreads();
#pragma unroll 2
        for (int kq = 0; kq < 16; ++kq) {
            float4 av[8];
#pragma unroll
            for (int i = 0; i < 8; ++i)
                av[i] = *reinterpret_cast<const float4*>(sA + (r0 + i) * ASTR + k0 + kq * 4);
#pragma unroll
            for (int t = 0; t < 4; ++t) {
                const float* wr = sW + (kq * 4 + t) * Hdim + c0;
                ulonglong2 wA = *reinterpret_cast<const ulonglong2*>(wr);
                ulonglong2 wB = *reinterpret_cast<const ulonglong2*>(wr + 4);
#pragma unroll
                for (int i = 0; i < 8; ++i) {
                    float a = reinterpret_cast<const float*>(&av[i])[t];
                    ull aa; PACK_DUP_F32X2(aa, a);
                    FMA_F32X2(acc[i][0], aa, wA.x, acc[i][0]);
                    FMA_F32X2(acc[i][1], aa, wA.y, acc[i][1]);
                    FMA_F32X2(acc[i][2], aa, wB.x, acc[i][2]);
                    FMA_F32X2(acc[i][3], aa, wB.y, acc[i][3]);
                }
            }
        }
        __syncthreads();
    }
}

__device__ __forceinline__ void zero_acc2(ull (&acc)[8][4]) {
#pragma unroll
    for (int i = 0; i < 8; ++i)
#pragma unroll
        for (int j = 0; j < 4; ++j) acc[i][j] = 0ull;
}

__device__ __forceinline__ void epi_bias_relu(ull (&acc)[8][4],
                                              const float* __restrict__ b,
                                              float* __restrict__ sA,
                                              int r0, int c0)
{
    float4 bv0 = *reinterpret_cast<const float4*>(b + c0);
    float4 bv1 = *reinterpret_cast<const float4*>(b + c0 + 4);
    const float bv[8] = {bv0.x, bv0.y, bv0.z, bv0.w, bv1.x, bv1.y, bv1.z, bv1.w};
#pragma unroll
    for (int i = 0; i < 8; ++i) {
        float v[8];
#pragma unroll
        for (int jj = 0; jj < 4; ++jj) {
            float lo, hi; UNPACK_F32X2(lo, hi, acc[i][jj]);
            lo += bv[2 * jj];     hi += bv[2 * jj + 1];
            v[2 * jj]     = lo > 0.f ? lo : 0.f;
            v[2 * jj + 1] = hi > 0.f ? hi : 0.f;
        }
        *reinterpret_cast<float4*>(sA + (r0 + i) * ASTR_SMALL + c0) =
            make_float4(v[0], v[1], v[2], v[3]);
        *reinterpret_cast<float4*>(sA + (r0 + i) * ASTR_SMALL + c0 + 4) =
            make_float4(v[4], v[5], v[6], v[7]);
    }
}

// MODE 0: nem — in=[x[esrc[e]], ef[e]]               (K=256), out -> x[edst[e]]        (set)
// MODE 1: mg  — in=[x[esrc[s+r]], x[esrc[s+half+r]]] (K=256), out -> x[edst[s+half+r]] (set)
// MODE 2: mr  — in=[x[edst[e]], state[e]]            (K=129), out -> x[esrc[e]] += out
template<int MODE>
__global__ void __launch_bounds__(128)
mlp_big(float* __restrict__ x,
        const float* __restrict__ ef,
        const int* __restrict__ esrc,
        const int* __restrict__ edst,
        const float* __restrict__ est,
        const float* __restrict__ w0, const float* __restrict__ b0,
        const float* __restrict__ w1, const float* __restrict__ b1,
        const float* __restrict__ w2, const float* __restrict__ b2,
        int s, int half, int nrows)
{
    constexpr int ASTR0 = (MODE == 2) ? ASTR_SMALL : ASTR_BIG;
    extern __shared__ float sm[];
    float* sA = sm;
    float* sW = sm + 64 * ASTR0;

    const int tid = threadIdx.x;
    const int cx = tid & 15, ry = tid >> 4;      // 16 col-groups x 8 row-groups
    const int c0 = cx * 8, r0 = ry * 8;
    const int row_base = blockIdx.x * 64;

    // ---- gather inputs into sA ----
    if (MODE == 0 || MODE == 1) {
        for (int idx = tid; idx < 64 * 64; idx += 128) {
            int r = idx >> 6, c4 = idx & 63;
            int row = row_base + r;
            if (row < nrows) {
                float4 v;
                if (c4 < 32) {
                    int node = esrc[s + row];
                    v = reinterpret_cast<const float4*>(x + (size_t)node * Hdim)[c4];
                } else if (MODE == 0) {
                    v = reinterpret_cast<const float4*>(ef + (size_t)(s + row) * Hdim)[c4 - 32];
                } else {
                    int node = esrc[s + half + row];
                    v = reinterpret_cast<const float4*>(x + (size_t)node * Hdim)[c4 - 32];
                }
                reinterpret_cast<float4*>(sA + r * ASTR_BIG)[c4] = v;
            }
        }
    } else {
        for (int idx = tid; idx < 64 * 32; idx += 128) {
            int r = idx >> 5, c4 = idx & 31;
            int row = row_base + r;
            if (row < nrows) {
                int node = edst[s + row];
                float4 v = reinterpret_cast<const float4*>(x + (size_t)node * Hdim)[c4];
                reinterpret_cast<float4*>(sA + r * ASTR_SMALL)[c4] = v;
            }
        }
        for (int r = tid; r < 64; r += 128) {
            int row = row_base + r;
            sA[r * ASTR_SMALL + 128] = (row < nrows) ? est[s + row] : 0.f;
        }
    }
    __syncthreads();

    ull acc[8][4];

    // ---- layer 0 ----
    zero_acc2(acc);
    if (MODE == 2) {
        layer_acc2<128, ASTR_SMALL>(sA, sW, w0, tid, r0, c0, acc);
        // state column: row 128 of w0, straight from global (L2-hot)
        const float* wsr = w0 + (size_t)128 * Hdim + c0;
        ulonglong2 wsA = *reinterpret_cast<const ulonglong2*>(wsr);
        ulonglong2 wsB = *reinterpret_cast<const ulonglong2*>(wsr + 4);
#pragma unroll
        for (int i = 0; i < 8; ++i) {
            float stv = sA[(r0 + i) * ASTR_SMALL + 128];
            ull aa; PACK_DUP_F32X2(aa, stv);
            FMA_F32X2(acc[i][0], aa, wsA.x, acc[i][0]);
            FMA_F32X2(acc[i][1], aa, wsA.y, acc[i][1]);
            FMA_F32X2(acc[i][2], aa, wsB.x, acc[i][2]);
            FMA_F32X2(acc[i][3], aa, wsB.y, acc[i][3]);
        }
    } else {
        layer_acc2<256, ASTR_BIG>(sA, sW, w0, tid, r0, c0, acc);
    }
    epi_bias_relu(acc, b0, sA, r0, c0);
    __syncthreads();

    // ---- layer 1 ----
    zero_acc2(acc);
    layer_acc2<128, ASTR_SMALL>(sA, sW, w1, tid, r0, c0, acc);
    epi_bias_relu(acc, b1, sA, r0, c0);
    __syncthreads();

    // ---- layer 2 + scatter ----
    zero_acc2(acc);
    layer_acc2<128, ASTR_SMALL>(sA, sW, w2, tid, r0, c0, acc);
    {
        float4 bv0 = *reinterpret_cast<const float4*>(b2 + c0);
        float4 bv1 = *reinterpret_cast<const float4*>(b2 + c0 + 4);
        const float bv[8] = {bv0.x, bv0.y, bv0.z, bv0.w, bv1.x, bv1.y, bv1.z, bv1.w};
#pragma unroll
        for (int i = 0; i < 8; ++i) {
            int row = row_base + r0 + i;
            if (row >= nrows) continue;
            float v[8];
#pragma unroll
            for (int jj = 0; jj < 4; ++jj) {
                float lo, hi; UNPACK_F32X2(lo, hi, acc[i][jj]);
                v[2 * jj]     = lo + bv[2 * jj];
                v[2 * jj + 1] = hi + bv[2 * jj + 1];
            }

            int node;
            if (MODE == 0)      node = edst[s + row];
            else if (MODE == 1) node = edst[s + half + row];
            else                node = esrc[s + row];

            float* p = x + (size_t)node * Hdim + c0;
            if (MODE == 2) {
                float4 o0 = *reinterpret_cast<const float4*>(p);
                float4 o1 = *reinterpret_cast<const float4*>(p + 4);
                v[0] += o0.x; v[1] += o0.y; v[2] += o0.z; v[3] += o0.w;
                v[4] += o1.x; v[5] += o1.y; v[6] += o1.z; v[7] += o1.w;
            }
            *reinterpret_cast<float4*>(p)     = make_float4(v[0], v[1], v[2], v[3]);
            *reinterpret_cast<float4*>(p + 4) = make_float4(v[4], v[5], v[6], v[7]);
        }
    }
}

// =============== SMALL kernel: 16-row tiles, 256 threads, 1x8/thread =======

template<int K, int ASTR>
__device__ __forceinline__ void layer_acc_s(const float* __restrict__ sA,
                                            float* __restrict__ sW,
                                            const float* __restrict__ w,
                                            int tid, int r0, int c0,
                                            float (&acc)[8])
{
#pragma unroll 1
    for (int k0 = 0; k0 < K; k0 += 64) {
        for (int idx = tid; idx < 64 * 32; idx += 256) {
            reinterpret_cast<float4*>(sW)[idx] =
                reinterpret_cast<const float4*>(w + (size_t)k0 * Hdim)[idx];
        }
        __syncthreads();
#pragma unroll 4
        for (int kq = 0; kq < 16; ++kq) {
            float4 av = *reinterpret_cast<const float4*>(sA + r0 * ASTR + k0 + kq * 4);
#pragma unroll
            for (int t = 0; t < 4; ++t) {
                const float* wr = sW + (kq * 4 + t) * Hdim + c0;
                float4 w0v = *reinterpret_cast<const float4*>(wr);
                float4 w1v = *reinterpret_cast<const float4*>(wr + 4);
                float a = reinterpret_cast<const float*>(&av)[t];
                acc[0] = fmaf(a, w0v.x, acc[0]);
                acc[1] = fmaf(a, w0v.y, acc[1]);
                acc[2] = fmaf(a, w0v.z, acc[2]);
                acc[3] = fmaf(a, w0v.w, acc[3]);
                acc[4] = fmaf(a, w1v.x, acc[4]);
                acc[5] = fmaf(a, w1v.y, acc[5]);
                acc[6] = fmaf(a, w1v.z, acc[6]);
                acc[7] = fmaf(a, w1v.w, acc[7]);
            }
        }
        __syncthreads();
    }
}

template<int MODE>
__global__ void __launch_bounds__(256)
mlp_small(float* __restrict__ x,
          const float* __restrict__ ef,
          const int* __restrict__ esrc,
          const int* __restrict__ edst,
          const float* __restrict__ est,
          const float* __restrict__ w0, const float* __restrict__ b0,
          const float* __restrict__ w1, const float* __restrict__ b1,
          const float* __restrict__ w2, const float* __restrict__ b2,
          int s, int half, int nrows)
{
    extern __shared__ float sm[];
    float* sA = sm;
    float* sW = sm + 16 * ASTR_BIG;

    const int tid = threadIdx.x;
    const int cx = tid & 15, ry = tid >> 4;      // 16 col-groups x 16 rows
    const int c0 = cx * 8, r0 = ry;
    const int row_base = blockIdx.x * 16;

    if (MODE == 0 || MODE == 1) {
        for (int idx = tid; idx < 16 * 64; idx += 256) {
            int r = idx >> 6, c4 = idx & 63;
            int row = row_base + r;
            if (row < nrows) {
                float4 v;
                if (c4 < 32) {
                    int node = esrc[s + row];
                    v = reinterpret_cast<const float4*>(x + (size_t)node * Hdim)[c4];
                } else if (MODE == 0) {
                    v = reinterpret_cast<const float4*>(ef + (size_t)(s + row) * Hdim)[c4 - 32];
                } else {
                    int node = esrc[s + half + row];
                    v = reinterpret_cast<const float4*>(x + (size_t)node * Hdim)[c4 - 32];
                }
                reinterpret_cast<float4*>(sA + r * ASTR_BIG)[c4] = v;
            }
        }
    } else {
        for (int idx = tid; idx < 16 * 32; idx += 256) {
            int r = idx >> 5, c4 = idx & 31;
            int row = row_base + r;
            if (row < nrows) {
                int node = edst[s + row];
                float4 v = reinterpret_cast<const float4*>(x + (size_t)node * Hdim)[c4];
                reinterpret_cast<float4*>(sA + r * ASTR_SMALL)[c4] = v;
            }
        }
        for (int r = tid; r < 16; r += 256) {
            int row = row_base + r;
            sA[r * ASTR_SMALL + 128] = (row < nrows) ? est[s + row] : 0.f;
        }
    }
    __syncthreads();

    float acc[8];

    // ---- layer 0 ----
#pragma unroll
    for (int j = 0; j < 8; ++j) acc[j] = 0.f;
    if (MODE == 2) {
        layer_acc_s<128, ASTR_SMALL>(sA, sW, w0, tid, r0, c0, acc);
        const float* wsr = w0 + (size_t)128 * Hdim + c0;
        float stv = sA[r0 * ASTR_SMALL + 128];
#pragma unroll
        for (int j = 0; j < 8; ++j) acc[j] = fmaf(stv, wsr[j], acc[j]);
    } else {
        layer_acc_s<256, ASTR_BIG>(sA, sW, w0, tid, r0, c0, acc);
    }
    {
#pragma unroll
        for (int j = 0; j < 8; ++j) {
            float v = acc[j] + b0[c0 + j];
            acc[j] = v > 0.f ? v : 0.f;
        }
        *reinterpret_cast<float4*>(sA + r0 * ASTR_SMALL + c0) =
            make_float4(acc[0], acc[1], acc[2], acc[3]);
        *reinterpret_cast<float4*>(sA + r0 * ASTR_SMALL + c0 + 4) =
            make_float4(acc[4], acc[5], acc[6], acc[7]);
    }
    __syncthreads();

    // ---- layer 1 ----
#pragma unroll
    for (int j = 0; j < 8; ++j) acc[j] = 0.f;
    layer_acc_s<128, ASTR_SMALL>(sA, sW, w1, tid, r0, c0, acc);
    {
#pragma unroll
        for (int j = 0; j < 8; ++j) {
            float v = acc[j] + b1[c0 + j];
            acc[j] = v > 0.f ? v : 0.f;
        }
        *reinterpret_cast<float4*>(sA + r0 * ASTR_SMALL + c0) =
            make_float4(acc[0], acc[1], acc[2], acc[3]);
        *reinterpret_cast<float4*>(sA + r0 * ASTR_SMALL + c0 + 4) =
            make_float4(acc[4], acc[5], acc[6], acc[7]);
    }
    __syncthreads();

    // ---- layer 2 + scatter ----
#pragma unroll
    for (int j = 0; j < 8; ++j) acc[j] = 0.f;
    layer_acc_s<128, ASTR_SMALL>(sA, sW, w2, tid, r0, c0, acc);
    {
        int row = row_base + r0;
        if (row < nrows) {
#pragma unroll
            for (int j = 0; j < 8; ++j) acc[j] += b2[c0 + j];

            int node;
            if (MODE == 0)      node = edst[s + row];
            else if (MODE == 1) node = edst[s + half + row];
            else                node = esrc[s + row];

            float* p = x + (size_t)node * Hdim + c0;
            if (MODE == 2) {
                float4 o0 = *reinterpret_cast<const float4*>(p);
                float4 o1 = *reinterpret_cast<const float4*>(p + 4);
                acc[0] += o0.x; acc[1] += o0.y; acc[2] += o0.z; acc[3] += o0.w;
                acc[4] += o1.x; acc[5] += o1.y; acc[6] += o1.z; acc[7] += o1.w;
            }
            *reinterpret_cast<float4*>(p)     = make_float4(acc[0], acc[1], acc[2], acc[3]);
            *reinterpret_cast<float4*>(p + 4) = make_float4(acc[4], acc[5], acc[6], acc[7]);
        }
    }
}

// copy only leaf rows of x (everything else is provably overwritten)
__global__ void leaf_copy_kernel(float* __restrict__ x, const float* __restrict__ x_in)
{
    int idx = blockIdx.x * blockDim.x + threadIdx.x;   // over NL*32 float4s
    if (idx >= NL * 32) return;
    int r = idx >> 5, c4 = idx & 31;
    int b = r >> 13, leaf = r & (NLEAF - 1);
    size_t node = (size_t)b * NPT + leaf;
    reinterpret_cast<float4*>(x + node * Hdim)[c4] =
        reinterpret_cast<const float4*>(x_in + node * Hdim)[c4];
}

extern "C" void kernel_launch(void* const* d_in, const int* in_sizes, int n_in,
                              void* d_out, int out_size)
{
    (void)n_in; (void)out_size;

    const float* x_in = (const float*)d_in[0];
    const int*   esrc = (const int*)  d_in[1];
    const int*   edst = (const int*)  d_in[2];
    const float* est  = (const float*)d_in[3];
    const float* ef   = (const float*)d_in[4];

    int wb = (in_sizes[5] == 1) ? 6 : 5;   // input 5 = scalar gcmn_depth

    const float* nem_w0 = (const float*)d_in[wb + 0];
    const float* nem_b0 = (const float*)d_in[wb + 1];
    const float* nem_w1 = (const float*)d_in[wb + 2];
    const float* nem_b1 = (const float*)d_in[wb + 3];
    const float* nem_w2 = (const float*)d_in[wb + 4];
    const float* nem_b2 = (const float*)d_in[wb + 5];
    const float* mg_w0  = (const float*)d_in[wb + 6];
    const float* mg_b0  = (const float*)d_in[wb + 7];
    const float* mg_w1  = (const float*)d_in[wb + 8];
    const float* mg_b1  = (const float*)d_in[wb + 9];
    const float* mg_w2  = (const float*)d_in[wb + 10];
    const float* mg_b2  = (const float*)d_in[wb + 11];
    const float* mr_w0  = (const float*)d_in[wb + 12];
    const float* mr_b0  = (const float*)d_in[wb + 13];
    const float* mr_w1  = (const float*)d_in[wb + 14];
    const float* mr_b1  = (const float*)d_in[wb + 15];
    const float* mr_w2  = (const float*)d_in[wb + 16];
    const float* mr_b2  = (const float*)d_in[wb + 17];

    float* x = (float*)d_out;

    cudaFuncSetAttribute(mlp_big<0>, cudaFuncAttributeMaxDynamicSharedMemorySize, SMEM_BIG_01);
    cudaFuncSetAttribute(mlp_big<1>, cudaFuncAttributeMaxDynamicSharedMemorySize, SMEM_BIG_01);
    cudaFuncSetAttribute(mlp_big<2>, cudaFuncAttributeMaxDynamicSharedMemorySize, SMEM_BIG_2);
    cudaFuncSetAttribute(mlp_small<1>, cudaFuncAttributeMaxDynamicSharedMemorySize, SMEM_SMALL);
    cudaFuncSetAttribute(mlp_small<2>, cudaFuncAttributeMaxDynamicSharedMemorySize, SMEM_SMALL);

    // init: only leaf rows need the original x
    leaf_copy_kernel<<<(NL * 32 + 255) / 256, 256>>>(x, x_in);

    // edge-block layout: block 0 = leaf edges (NL), block d (1..13): 8*(NLEAF>>(d-1)) edges
    int cnt[14], st[14];
    cnt[0] = NL; st[0] = 0;
    for (int d = 1; d < DEPTH; ++d) {
        cnt[d] = 8 * (NLEAF >> (d - 1));
        st[d] = st[d - 1] + cnt[d - 1];
    }

    constexpr int SMALL_THRESH = 2048;

    // ---- nem: leaf -> level-1 ----
    mlp_big<0><<<NL / 64, 128, SMEM_BIG_01>>>(
        x, ef, esrc, edst, nullptr,
        nem_w0, nem_b0, nem_w1, nem_b1, nem_w2, nem_b2, 0, 0, NL);

    // ---- mg: upward merge, levels 1..13 (sequential) ----
    for (int d = 1; d < DEPTH; ++d) {
        int half = cnt[d] / 2;
        if (half <= SMALL_THRESH)
            mlp_small<1><<<(half + 15) / 16, 256, SMEM_SMALL>>>(
                x, nullptr, esrc, edst, nullptr,
                mg_w0, mg_b0, mg_w1, mg_b1, mg_w2, mg_b2, st[d], half, half);
        else
            mlp_big<1><<<(half + 63) / 64, 128, SMEM_BIG_01>>>(
                x, nullptr, esrc, edst, nullptr,
                mg_w0, mg_b0, mg_w1, mg_b1, mg_w2, mg_b2, st[d], half, half);
    }

    // ---- mr: downward, depth 14..1 (sequential) ----
    for (int depth = DEPTH; depth >= 1; --depth) {
        int sE, m;
        if (depth == 1) { sE = 0; m = NL; }
        else            { sE = st[depth - 1]; m = cnt[depth - 1]; }
        if (m <= SMALL_THRESH)
            mlp_small<2><<<(m + 15) / 16, 256, SMEM_SMALL>>>(
                x, nullptr, esrc, edst, est,
                mr_w0, mr_b0, mr_w1, mr_b1, mr_w2, mr_b2, sE, 0, m);
        else
            mlp_big<2><<<(m + 63) / 64, 128, SMEM_BIG_2>>>(
                x, nullptr, esrc, edst, est,
                mr_w0, mr_b0, mr_w1, mr_b1, mr_w2, mr_b2, sE, 0, m);
    }
}